// round 1
// baseline (speedup 1.0000x reference)
#include <cuda_runtime.h>
#include <cuda_bf16.h>

// Problem constants (match reference)
#define B_SZ       128
#define S_SZ       4096
#define TOK        64          // token_dim
#define EFF        60          // token_dim - 4
#define NF         20          // num features
#define H0         256
#define H1         128
#define H2         64
#define OUT        3
#define CHUNKS     4           // seq chunks per batch
#define CHUNK_S    (S_SZ / CHUNKS)   // 1024 tokens per chunk

// Scratch: partial column sums per (batch, chunk): [B, CHUNKS, TOK]
__device__ float g_partial[B_SZ * CHUNKS * TOK];

// ---------------------------------------------------------------------------
// Kernel 1: streaming column-sum over the sequence dimension.
// grid = B*CHUNKS blocks, 256 threads. Each block sums TOK=64 columns over
// CHUNK_S=1024 tokens. Each thread owns one float4 lane group (i % 16 is
// constant because the stride 256 is a multiple of 16), so accumulation is
// conflict-free and fully vectorized.
// ---------------------------------------------------------------------------
__global__ __launch_bounds__(256, 8)
void mean_sum_kernel(const float* __restrict__ x) {
    const int b = blockIdx.x >> 2;        // batch
    const int c = blockIdx.x & 3;         // chunk
    const int t = threadIdx.x;            // 0..255

    const float4* __restrict__ p =
        (const float4*)(x + ((size_t)b * S_SZ + (size_t)c * CHUNK_S) * TOK);

    // CHUNK_S * TOK / 4 = 1024*16 = 16384 float4 per block; 64 per thread.
    float4 acc = make_float4(0.f, 0.f, 0.f, 0.f);
    #pragma unroll 16
    for (int i = t; i < CHUNK_S * (TOK / 4); i += 256) {
        float4 v = __ldcs(&p[i]);         // streaming: x is touched once
        acc.x += v.x; acc.y += v.y; acc.z += v.z; acc.w += v.w;
    }

    __shared__ float4 sm[256];
    sm[t] = acc;
    __syncthreads();

    // 16 column groups (g = t % 16); reduce the 16 threads of each group.
    if (t < 16) {
        float4 s = make_float4(0.f, 0.f, 0.f, 0.f);
        #pragma unroll
        for (int k = 0; k < 16; k++) {
            float4 v = sm[t + k * 16];
            s.x += v.x; s.y += v.y; s.z += v.z; s.w += v.w;
        }
        float* dst = &g_partial[(size_t)(b * CHUNKS + c) * TOK + t * 4];
        dst[0] = s.x; dst[1] = s.y; dst[2] = s.z; dst[3] = s.w;
    }
}

// ---------------------------------------------------------------------------
// Kernel 2: per-batch feature extraction + MLP.
// grid = B blocks, 256 threads. Activations live in shared memory; each
// layer maps one output neuron to one thread. Weights stay hot in L2.
// ---------------------------------------------------------------------------
__global__ __launch_bounds__(256, 4)
void mlp_kernel(const float* __restrict__ w_ext, const float* __restrict__ b_ext,
                const float* __restrict__ w0, const float* __restrict__ b0,
                const float* __restrict__ w1, const float* __restrict__ b1,
                const float* __restrict__ w2, const float* __restrict__ b2,
                const float* __restrict__ w3, const float* __restrict__ b3,
                float* __restrict__ out) {
    const int b = blockIdx.x;
    const int t = threadIdx.x;

    __shared__ float xm[TOK];
    __shared__ float feats[NF];
    __shared__ float a0[H0];
    __shared__ float a1[H1];
    __shared__ float a2[H2];

    // Reduce chunk partials -> mean
    if (t < TOK) {
        float s = 0.f;
        #pragma unroll
        for (int c = 0; c < CHUNKS; c++)
            s += g_partial[(size_t)(b * CHUNKS + c) * TOK + t];
        xm[t] = s * (1.0f / (float)S_SZ);
    }
    __syncthreads();

    // Extractor: 20 outputs, dot over EFF=60
    if (t < NF) {
        const float* __restrict__ w = w_ext + t * EFF;
        float s = b_ext[t];
        #pragma unroll
        for (int k = 0; k < EFF; k++) s = fmaf(xm[k], w[k], s);
        feats[t] = s;
    }
    __syncthreads();

    // Layer 0: 20 -> 256 + ReLU (all 256 threads)
    {
        const float* __restrict__ w = w0 + t * NF;
        float s = b0[t];
        #pragma unroll
        for (int k = 0; k < NF; k++) s = fmaf(feats[k], w[k], s);
        a0[t] = fmaxf(s, 0.f);
    }
    __syncthreads();

    // Layer 1: 256 -> 128 + ReLU (float4 over the 256-dot)
    if (t < H1) {
        const float4* __restrict__ w = (const float4*)(w1 + t * H0);
        const float4* __restrict__ h = (const float4*)a0;
        float s = b1[t];
        #pragma unroll 16
        for (int k = 0; k < H0 / 4; k++) {
            float4 wv = w[k];
            float4 hv = h[k];
            s = fmaf(hv.x, wv.x, s);
            s = fmaf(hv.y, wv.y, s);
            s = fmaf(hv.z, wv.z, s);
            s = fmaf(hv.w, wv.w, s);
        }
        a1[t] = fmaxf(s, 0.f);
    }
    __syncthreads();

    // Layer 2: 128 -> 64 + ReLU
    if (t < H2) {
        const float4* __restrict__ w = (const float4*)(w2 + t * H1);
        const float4* __restrict__ h = (const float4*)a1;
        float s = b2[t];
        #pragma unroll 8
        for (int k = 0; k < H1 / 4; k++) {
            float4 wv = w[k];
            float4 hv = h[k];
            s = fmaf(hv.x, wv.x, s);
            s = fmaf(hv.y, wv.y, s);
            s = fmaf(hv.z, wv.z, s);
            s = fmaf(hv.w, wv.w, s);
        }
        a2[t] = fmaxf(s, 0.f);
    }
    __syncthreads();

    // Layer 3: 64 -> 3 (no activation)
    if (t < OUT) {
        const float4* __restrict__ w = (const float4*)(w3 + t * H2);
        const float4* __restrict__ h = (const float4*)a2;
        float s = b3[t];
        #pragma unroll
        for (int k = 0; k < H2 / 4; k++) {
            float4 wv = w[k];
            float4 hv = h[k];
            s = fmaf(hv.x, wv.x, s);
            s = fmaf(hv.y, wv.y, s);
            s = fmaf(hv.z, wv.z, s);
            s = fmaf(hv.w, wv.w, s);
        }
        out[b * OUT + t] = s;
    }
}

extern "C" void kernel_launch(void* const* d_in, const int* in_sizes, int n_in,
                              void* d_out, int out_size) {
    const float* x     = (const float*)d_in[0];
    const float* w_ext = (const float*)d_in[1];
    const float* b_ext = (const float*)d_in[2];
    const float* w0    = (const float*)d_in[3];
    const float* b0    = (const float*)d_in[4];
    const float* w1    = (const float*)d_in[5];
    const float* b1    = (const float*)d_in[6];
    const float* w2    = (const float*)d_in[7];
    const float* b2    = (const float*)d_in[8];
    const float* w3    = (const float*)d_in[9];
    const float* b3    = (const float*)d_in[10];
    float* out = (float*)d_out;

    mean_sum_kernel<<<B_SZ * CHUNKS, 256>>>(x);
    mlp_kernel<<<B_SZ, 256>>>(w_ext, b_ext, w0, b0, w1, b1, w2, b2, w3, b3, out);
}

// round 4
// speedup vs baseline: 1.1249x; 1.1249x over previous
#include <cuda_runtime.h>
#include <cuda_bf16.h>

// Problem constants (match reference)
#define B_SZ       128
#define S_SZ       4096
#define TOK        64          // token_dim
#define EFF        60          // token_dim - 4
#define NF         20          // num features
#define H0         256
#define H1         128
#define H2         64
#define OUT        3
#define NT         512         // threads per block

// ---------------------------------------------------------------------------
// One block per batch: stream-reduce the whole batch (1 MB), then run the
// per-batch MLP in the same block. No cross-block communication.
// grid = 128 blocks (single wave on 148 SMs), 512 threads.
// ---------------------------------------------------------------------------
__global__ __launch_bounds__(NT, 1)
void fused_kernel(const float* __restrict__ x,
                  const float* __restrict__ w_ext, const float* __restrict__ b_ext,
                  const float* __restrict__ w0, const float* __restrict__ b0,
                  const float* __restrict__ w1, const float* __restrict__ b1,
                  const float* __restrict__ w2, const float* __restrict__ b2,
                  const float* __restrict__ w3, const float* __restrict__ b3,
                  float* __restrict__ out) {
    const int b = blockIdx.x;             // batch
    const int t = threadIdx.x;            // 0..511

    __shared__ float4 sm[NT];             // 8 KB reduction buffer
    __shared__ float xm[TOK];
    __shared__ float feats[NF];
    __shared__ float a0[H0];
    __shared__ float a1[H1];
    __shared__ float a2[H2];

    // ---------------- Phase 1: streaming column sum over the whole batch ---
    {
        const float4* __restrict__ p = (const float4*)(x + (size_t)b * S_SZ * TOK);
        // 4096 tokens * 16 float4/token = 65536 float4; 128 per thread.
        // Stride NT=512 is a multiple of 16, so each thread stays on one
        // float4 column-group (t & 15) -> conflict-free accumulation.
        float4 acc = make_float4(0.f, 0.f, 0.f, 0.f);
        #pragma unroll 8
        for (int i = t; i < S_SZ * (TOK / 4); i += NT) {
            float4 v = __ldcs(&p[i]);     // streaming: x touched exactly once
            acc.x += v.x; acc.y += v.y; acc.z += v.z; acc.w += v.w;
        }
        sm[t] = acc;
        __syncthreads();

        // 16 column groups; 32 contributing threads per group.
        if (t < 16) {
            float4 s = make_float4(0.f, 0.f, 0.f, 0.f);
            #pragma unroll
            for (int k = 0; k < 32; k++) {
                float4 v = sm[t + k * 16];
                s.x += v.x; s.y += v.y; s.z += v.z; s.w += v.w;
            }
            const float inv = 1.0f / (float)S_SZ;
            xm[t * 4 + 0] = s.x * inv;
            xm[t * 4 + 1] = s.y * inv;
            xm[t * 4 + 2] = s.z * inv;
            xm[t * 4 + 3] = s.w * inv;
        }
        __syncthreads();
    }

    // ---------------- Phase 2: per-batch MLP -------------------------------
    // Extractor: 20 outputs, dot over EFF=60; 4 accumulators break the chain
    if (t < NF) {
        const float* __restrict__ w = w_ext + t * EFF;
        float s0 = b_ext[t], s1 = 0.f, s2 = 0.f, s3 = 0.f;
        #pragma unroll
        for (int k = 0; k < EFF; k += 4) {
            s0 = fmaf(xm[k + 0], w[k + 0], s0);
            s1 = fmaf(xm[k + 1], w[k + 1], s1);
            s2 = fmaf(xm[k + 2], w[k + 2], s2);
            s3 = fmaf(xm[k + 3], w[k + 3], s3);
        }
        feats[t] = (s0 + s1) + (s2 + s3);
    }
    __syncthreads();

    // Layer 0: 20 -> 256 + ReLU (one neuron per thread, threads 0..255)
    if (t < H0) {
        const float* __restrict__ w = w0 + t * NF;
        float s0 = b0[t], s1 = 0.f;
        #pragma unroll
        for (int k = 0; k < NF; k += 2) {
            s0 = fmaf(feats[k + 0], w[k + 0], s0);
            s1 = fmaf(feats[k + 1], w[k + 1], s1);
        }
        a0[t] = fmaxf(s0 + s1, 0.f);
    }
    __syncthreads();

    // Layer 1: 256 -> 128 + ReLU. Four threads per neuron (j = t>>2),
    // each handles 64 elements (16 float4), then 2-step shfl reduction.
    {
        const int j = t >> 2;             // neuron 0..127
        const int q = t & 3;
        const float4* __restrict__ w = (const float4*)(w1 + j * H0) + q * 16;
        const float4* __restrict__ hv = (const float4*)a0 + q * 16;
        float s0 = 0.f, s1 = 0.f, s2 = 0.f, s3 = 0.f;
        #pragma unroll
        for (int k = 0; k < 16; k++) {
            float4 wv = w[k];
            float4 av = hv[k];
            s0 = fmaf(av.x, wv.x, s0);
            s1 = fmaf(av.y, wv.y, s1);
            s2 = fmaf(av.z, wv.z, s2);
            s3 = fmaf(av.w, wv.w, s3);
        }
        float s = (s0 + s1) + (s2 + s3);
        s += __shfl_xor_sync(0xFFFFFFFF, s, 1);
        s += __shfl_xor_sync(0xFFFFFFFF, s, 2);
        if (q == 0) a1[j] = fmaxf(s + b1[j], 0.f);
    }
    __syncthreads();

    // Layer 2: 128 -> 64 + ReLU. Eight threads per neuron (j = t>>3),
    // each handles 16 elements (4 float4), then 3-step shfl reduction.
    {
        const int j = t >> 3;             // neuron 0..63
        const int o = t & 7;
        const float4* __restrict__ w = (const float4*)(w2 + j * H1) + o * 4;
        const float4* __restrict__ hv = (const float4*)a1 + o * 4;
        float s0 = 0.f, s1 = 0.f, s2 = 0.f, s3 = 0.f;
        #pragma unroll
        for (int k = 0; k < 4; k++) {
            float4 wv = w[k];
            float4 av = hv[k];
            s0 = fmaf(av.x, wv.x, s0);
            s1 = fmaf(av.y, wv.y, s1);
            s2 = fmaf(av.z, wv.z, s2);
            s3 = fmaf(av.w, wv.w, s3);
        }
        float s = (s0 + s1) + (s2 + s3);
        s += __shfl_xor_sync(0xFFFFFFFF, s, 1);
        s += __shfl_xor_sync(0xFFFFFFFF, s, 2);
        s += __shfl_xor_sync(0xFFFFFFFF, s, 4);
        if (o == 0) a2[j] = fmaxf(s + b2[j], 0.f);
    }
    __syncthreads();

    // Layer 3: 64 -> 3 (no activation)
    if (t < OUT) {
        const float4* __restrict__ w = (const float4*)(w3 + t * H2);
        const float4* __restrict__ hv = (const float4*)a2;
        float s0 = b3[t], s1 = 0.f, s2 = 0.f, s3 = 0.f;
        #pragma unroll
        for (int k = 0; k < H2 / 4; k++) {
            float4 wv = w[k];
            float4 av = hv[k];
            s0 = fmaf(av.x, wv.x, s0);
            s1 = fmaf(av.y, wv.y, s1);
            s2 = fmaf(av.z, wv.z, s2);
            s3 = fmaf(av.w, wv.w, s3);
        }
        out[b * OUT + t] = (s0 + s1) + (s2 + s3);
    }
}

extern "C" void kernel_launch(void* const* d_in, const int* in_sizes, int n_in,
                              void* d_out, int out_size) {
    const float* x     = (const float*)d_in[0];
    const float* w_ext = (const float*)d_in[1];
    const float* b_ext = (const float*)d_in[2];
    const float* w0    = (const float*)d_in[3];
    const float* b0    = (const float*)d_in[4];
    const float* w1    = (const float*)d_in[5];
    const float* b1    = (const float*)d_in[6];
    const float* w2    = (const float*)d_in[7];
    const float* b2    = (const float*)d_in[8];
    const float* w3    = (const float*)d_in[9];
    const float* b3    = (const float*)d_in[10];
    float* out = (float*)d_out;

    fused_kernel<<<B_SZ, NT>>>(x, w_ext, b_ext, w0, b0, w1, b1,
                               w2, b2, w3, b3, out);
}